// round 3
// baseline (speedup 1.0000x reference)
#include <cuda_runtime.h>
#include <cuda_bf16.h>
#include <cstdint>

// Fused: 3x3 conv (reflect pad 1, 64->128 ch) + BatchNorm(inference) + LeakyReLU(0.01) + mask mul
// Direct fp32 conv with packed f32x2 FMA:
//  - per CTA: 64x16 pixels x 8 output channels
//  - per thread: 4x2 pixels x 8 oc = 32 packed f32x2 accumulators
//  - all weights for the CTA staged once (duplicated float2, 36.8KB smem)
//  - input tiles double-buffered via cp.async

#define H_IMG 512
#define W_IMG 512
#define CIN   64
#define COUT  128

#define BX  64
#define BY  16
#define PX  4
#define PY  2
#define BOC 8
#define TXN (BX/PX)    // 16
#define TYN (BY/PY)    // 8
#define NTH (TXN*TYN)  // 128
#define SSTR (BX+4)    // 68
#define HALO_ELEMS ((BY+2)*(BX+2))   // 18*66 = 1188

typedef unsigned long long u64;

__device__ __forceinline__ u64 pack2(float lo, float hi) {
    u64 r;
    asm("mov.b64 %0, {%1, %2};" : "=l"(r) : "f"(lo), "f"(hi));
    return r;
}
__device__ __forceinline__ void unpack2(u64 v, float& lo, float& hi) {
    asm("mov.b64 {%0, %1}, %2;" : "=f"(lo), "=f"(hi) : "l"(v));
}
__device__ __forceinline__ u64 fma2(u64 a, u64 b, u64 c) {
    u64 d;
    asm("fma.rn.f32x2 %0, %1, %2, %3;" : "=l"(d) : "l"(a), "l"(b), "l"(c));
    return d;
}
__device__ __forceinline__ void cp_async4(uint32_t saddr, const void* gptr) {
    asm volatile("cp.async.ca.shared.global [%0], [%1], 4;" :: "r"(saddr), "l"(gptr));
}
__device__ __forceinline__ void cp_commit() {
    asm volatile("cp.async.commit_group;");
}
template <int N>
__device__ __forceinline__ void cp_wait() {
    asm volatile("cp.async.wait_group %0;" :: "n"(N));
}

__global__ __launch_bounds__(NTH)
void conv_bn_lrelu_mask_kernel(
    const float* __restrict__ x,      // [64,512,512]
    const float* __restrict__ wgt,    // [128,64,3,3]
    const float* __restrict__ gamma,  // [128]
    const float* __restrict__ beta,   // [128]
    const float* __restrict__ mean,   // [128]
    const float* __restrict__ var,    // [128]
    const int*   __restrict__ mask,   // [128,512,512]
    float*       __restrict__ out)    // [128,512,512]
{
    __shared__ float  s_in[2][(BY + 2) * SSTR];          // 2 * 4896 B
    __shared__ float2 s_wall[CIN * BOC * 9];             // 36864 B, duplicated weights
    __shared__ float  s_scale[BOC];
    __shared__ float  s_shift[BOC];

    const int tid = threadIdx.x;
    const int bx0 = blockIdx.x * BX;
    const int by0 = blockIdx.y * BY;
    const int oc0 = blockIdx.z * BOC;

    if (tid < BOC) {
        const int oc = oc0 + tid;
        const float inv = rsqrtf(var[oc] + 1e-5f);
        const float sc = gamma[oc] * inv;
        s_scale[tid] = sc;
        s_shift[tid] = beta[oc] - mean[oc] * sc;
    }

    // ---- stage ALL weights for this oc-block once: [ci][o][k] duplicated ----
    // global index is contiguous: wgt[oc0*576 + i], i = (o*64+ci)*9+k
    {
        const float* wbase = wgt + (size_t)oc0 * (CIN * 9);
        for (int i = tid; i < BOC * CIN * 9; i += NTH) {
            const int o  = i / (CIN * 9);
            const int r  = i % (CIN * 9);
            const int ci = r / 9;
            const int k  = r % 9;
            const float w = wbase[i];
            s_wall[ci * (BOC * 9) + o * 9 + k] = make_float2(w, w);
        }
    }

    // ---- async-stage input tile for ci=0 ----
    auto stage_input = [&](int ci, int buf) {
        const float* xin = x + (size_t)ci * (H_IMG * W_IMG);
        for (int i = tid; i < HALO_ELEMS; i += NTH) {
            const int r = i / (BX + 2);
            const int c = i % (BX + 2);
            int gy = by0 - 1 + r;
            int gx = bx0 - 1 + c;
            gy = (gy < 0) ? 1 : ((gy >= H_IMG) ? (H_IMG - 2) : gy);
            gx = (gx < 0) ? 1 : ((gx >= W_IMG) ? (W_IMG - 2) : gx);
            cp_async4((uint32_t)__cvta_generic_to_shared(&s_in[buf][r * SSTR + c]),
                      &xin[gy * W_IMG + gx]);
        }
        cp_commit();
    };
    stage_input(0, 0);

    u64 acc[BOC][PY][2];
#pragma unroll
    for (int o = 0; o < BOC; o++)
#pragma unroll
        for (int py = 0; py < PY; py++) {
            acc[o][py][0] = 0ull;
            acc[o][py][1] = 0ull;
        }

    const int tx = tid % TXN;
    const int ty = tid / TXN;
    const int x0 = tx * PX;
    const int y0 = ty * PY;

    for (int ci = 0; ci < CIN; ci++) {
        const int cur = ci & 1;

        // prefetch next input tile into the other buffer
        if (ci + 1 < CIN) {
            stage_input(ci + 1, cur ^ 1);
            cp_wait<1>();   // wait for ci's group, keep ci+1's in flight
        } else {
            cp_wait<0>();
        }
        __syncthreads();    // ci's tile visible to all threads

        // ---- load input window (PY+2) x (PX+2) = 4 x 6, build 5 shifted pairs/row ----
        u64 prow[PY + 2][PX + 1];
#pragma unroll
        for (int r = 0; r < PY + 2; r++) {
            const float* row = &s_in[cur][(y0 + r) * SSTR + x0];
            float4 v4 = *reinterpret_cast<const float4*>(row);
            float2 v2 = *reinterpret_cast<const float2*>(row + 4);
            prow[r][0] = pack2(v4.x, v4.y);
            prow[r][1] = pack2(v4.y, v4.z);
            prow[r][2] = pack2(v4.z, v4.w);
            prow[r][3] = pack2(v4.w, v2.x);
            prow[r][4] = pack2(v2.x, v2.y);
        }

        // ---- accumulate: 8 oc x 2 rows x 2 pairs x 9 taps = 288 f32x2 FMA ----
        const u64* w64 = reinterpret_cast<const u64*>(s_wall + ci * (BOC * 9));
#pragma unroll
        for (int o = 0; o < BOC; o++) {
            u64 wq[9];
#pragma unroll
            for (int k = 0; k < 9; k++) wq[k] = w64[o * 9 + k];
#pragma unroll
            for (int py = 0; py < PY; py++) {
#pragma unroll
                for (int q = 0; q < 2; q++) {
                    u64 s = acc[o][py][q];
#pragma unroll
                    for (int ky = 0; ky < 3; ky++) {
#pragma unroll
                        for (int kx = 0; kx < 3; kx++) {
                            s = fma2(wq[ky * 3 + kx], prow[py + ky][2 * q + kx], s);
                        }
                    }
                    acc[o][py][q] = s;
                }
            }
        }

        __syncthreads();    // compute on buffer `cur` done before it is overwritten
    }

    // ---- epilogue: BN + LeakyReLU + mask, vectorized ----
#pragma unroll
    for (int o = 0; o < BOC; o++) {
        const float sc = s_scale[o];
        const float sh = s_shift[o];
        const int oc = oc0 + o;
#pragma unroll
        for (int py = 0; py < PY; py++) {
            const int gy = by0 + y0 + py;
            const size_t base = (((size_t)oc * H_IMG) + gy) * W_IMG + bx0 + x0;
            const int4 m = *reinterpret_cast<const int4*>(mask + base);
            float a0, a1, a2, a3;
            unpack2(acc[o][py][0], a0, a1);
            unpack2(acc[o][py][1], a2, a3);
            float4 v;
            float t;
            t = fmaf(a0, sc, sh); t = (t >= 0.0f) ? t : 0.01f * t; v.x = t * (float)m.x;
            t = fmaf(a1, sc, sh); t = (t >= 0.0f) ? t : 0.01f * t; v.y = t * (float)m.y;
            t = fmaf(a2, sc, sh); t = (t >= 0.0f) ? t : 0.01f * t; v.z = t * (float)m.z;
            t = fmaf(a3, sc, sh); t = (t >= 0.0f) ? t : 0.01f * t; v.w = t * (float)m.w;
            *reinterpret_cast<float4*>(out + base) = v;
        }
    }
}

extern "C" void kernel_launch(void* const* d_in, const int* in_sizes, int n_in,
                              void* d_out, int out_size) {
    const float* x     = (const float*)d_in[0];
    const float* wgt   = (const float*)d_in[1];
    const float* gamma = (const float*)d_in[2];
    const float* beta  = (const float*)d_in[3];
    const float* mean  = (const float*)d_in[4];
    const float* var   = (const float*)d_in[5];
    const int*   mask  = (const int*)d_in[6];
    float* out = (float*)d_out;

    dim3 block(NTH, 1, 1);
    dim3 grid(W_IMG / BX, H_IMG / BY, COUT / BOC);  // 8 x 32 x 16 = 4096 CTAs
    conv_bn_lrelu_mask_kernel<<<grid, block>>>(x, wgt, gamma, beta, mean, var, mask, out);
}

// round 4
// speedup vs baseline: 1.0018x; 1.0018x over previous
#include <cuda_runtime.h>
#include <cuda_bf16.h>
#include <cstdint>

// Fused: 3x3 conv (reflect pad 1, 64->128 ch) + BatchNorm(inference) + LeakyReLU(0.01) + mask mul
// Direct fp32 conv with packed f32x2 FMA.
// R4 change vs R3: weights loaded per-ky row (3 LDS.64, 6 regs live) instead of 9 taps
// upfront (18 regs) -> main-loop live set ~120 regs, no spills.

#define H_IMG 512
#define W_IMG 512
#define CIN   64
#define COUT  128

#define BX  64
#define BY  16
#define PX  4
#define PY  2
#define BOC 8
#define TXN (BX/PX)    // 16
#define TYN (BY/PY)    // 8
#define NTH (TXN*TYN)  // 128
#define SSTR (BX+4)    // 68
#define HALO_ELEMS ((BY+2)*(BX+2))   // 1188

typedef unsigned long long u64;

__device__ __forceinline__ u64 pack2(float lo, float hi) {
    u64 r;
    asm("mov.b64 %0, {%1, %2};" : "=l"(r) : "f"(lo), "f"(hi));
    return r;
}
__device__ __forceinline__ void unpack2(u64 v, float& lo, float& hi) {
    asm("mov.b64 {%0, %1}, %2;" : "=f"(lo), "=f"(hi) : "l"(v));
}
__device__ __forceinline__ u64 fma2(u64 a, u64 b, u64 c) {
    u64 d;
    asm("fma.rn.f32x2 %0, %1, %2, %3;" : "=l"(d) : "l"(a), "l"(b), "l"(c));
    return d;
}
__device__ __forceinline__ void cp_async4(uint32_t saddr, const void* gptr) {
    asm volatile("cp.async.ca.shared.global [%0], [%1], 4;" :: "r"(saddr), "l"(gptr));
}
__device__ __forceinline__ void cp_commit() {
    asm volatile("cp.async.commit_group;");
}
template <int N>
__device__ __forceinline__ void cp_wait() {
    asm volatile("cp.async.wait_group %0;" :: "n"(N));
}

__global__ __launch_bounds__(NTH, 4)
void conv_bn_lrelu_mask_kernel(
    const float* __restrict__ x,      // [64,512,512]
    const float* __restrict__ wgt,    // [128,64,3,3]
    const float* __restrict__ gamma,  // [128]
    const float* __restrict__ beta,   // [128]
    const float* __restrict__ mean,   // [128]
    const float* __restrict__ var,    // [128]
    const int*   __restrict__ mask,   // [128,512,512]
    float*       __restrict__ out)    // [128,512,512]
{
    __shared__ float  s_in[2][(BY + 2) * SSTR];          // 2 * 4896 B
    __shared__ float2 s_wall[CIN * BOC * 9];             // 36864 B, duplicated weights
    __shared__ float  s_scale[BOC];
    __shared__ float  s_shift[BOC];

    const int tid = threadIdx.x;
    const int bx0 = blockIdx.x * BX;
    const int by0 = blockIdx.y * BY;
    const int oc0 = blockIdx.z * BOC;

    if (tid < BOC) {
        const int oc = oc0 + tid;
        const float inv = rsqrtf(var[oc] + 1e-5f);
        const float sc = gamma[oc] * inv;
        s_scale[tid] = sc;
        s_shift[tid] = beta[oc] - mean[oc] * sc;
    }

    // ---- stage ALL weights for this oc-block once (duplicated float2) ----
    {
        const float* wbase = wgt + (size_t)oc0 * (CIN * 9);
        for (int i = tid; i < BOC * CIN * 9; i += NTH) {
            const int o  = i / (CIN * 9);
            const int r  = i % (CIN * 9);
            const int ci = r / 9;
            const int k  = r % 9;
            const float w = wbase[i];
            s_wall[ci * (BOC * 9) + o * 9 + k] = make_float2(w, w);
        }
    }

    auto stage_input = [&](int ci, int buf) {
        const float* xin = x + (size_t)ci * (H_IMG * W_IMG);
        for (int i = tid; i < HALO_ELEMS; i += NTH) {
            const int r = i / (BX + 2);
            const int c = i % (BX + 2);
            int gy = by0 - 1 + r;
            int gx = bx0 - 1 + c;
            gy = (gy < 0) ? 1 : ((gy >= H_IMG) ? (H_IMG - 2) : gy);
            gx = (gx < 0) ? 1 : ((gx >= W_IMG) ? (W_IMG - 2) : gx);
            cp_async4((uint32_t)__cvta_generic_to_shared(&s_in[buf][r * SSTR + c]),
                      &xin[gy * W_IMG + gx]);
        }
        cp_commit();
    };
    stage_input(0, 0);

    u64 acc[BOC][PY][2];
#pragma unroll
    for (int o = 0; o < BOC; o++)
#pragma unroll
        for (int py = 0; py < PY; py++) {
            acc[o][py][0] = 0ull;
            acc[o][py][1] = 0ull;
        }

    const int tx = tid % TXN;
    const int ty = tid / TXN;
    const int x0 = tx * PX;
    const int y0 = ty * PY;

    for (int ci = 0; ci < CIN; ci++) {
        const int cur = ci & 1;

        if (ci + 1 < CIN) {
            stage_input(ci + 1, cur ^ 1);
            cp_wait<1>();
        } else {
            cp_wait<0>();
        }
        __syncthreads();

        // ---- input window (PY+2) x (PX+2) = 4 x 6 -> 5 shifted pairs/row ----
        u64 prow[PY + 2][PX + 1];
#pragma unroll
        for (int r = 0; r < PY + 2; r++) {
            const float* row = &s_in[cur][(y0 + r) * SSTR + x0];
            float4 v4 = *reinterpret_cast<const float4*>(row);
            float2 v2 = *reinterpret_cast<const float2*>(row + 4);
            prow[r][0] = pack2(v4.x, v4.y);
            prow[r][1] = pack2(v4.y, v4.z);
            prow[r][2] = pack2(v4.z, v4.w);
            prow[r][3] = pack2(v4.w, v2.x);
            prow[r][4] = pack2(v2.x, v2.y);
        }

        // ---- accumulate: per (oc, ky): 3 weight LDS.64 live -> 12 FMA2 ----
        const u64* w64 = reinterpret_cast<const u64*>(s_wall + ci * (BOC * 9));
#pragma unroll
        for (int o = 0; o < BOC; o++) {
#pragma unroll
            for (int ky = 0; ky < 3; ky++) {
                const u64 w0 = w64[o * 9 + ky * 3 + 0];
                const u64 w1 = w64[o * 9 + ky * 3 + 1];
                const u64 w2 = w64[o * 9 + ky * 3 + 2];
#pragma unroll
                for (int py = 0; py < PY; py++) {
#pragma unroll
                    for (int q = 0; q < 2; q++) {
                        u64 s = acc[o][py][q];
                        s = fma2(w0, prow[py + ky][2 * q + 0], s);
                        s = fma2(w1, prow[py + ky][2 * q + 1], s);
                        s = fma2(w2, prow[py + ky][2 * q + 2], s);
                        acc[o][py][q] = s;
                    }
                }
            }
        }

        __syncthreads();
    }

    // ---- epilogue: BN + LeakyReLU + mask ----
#pragma unroll
    for (int o = 0; o < BOC; o++) {
        const float sc = s_scale[o];
        const float sh = s_shift[o];
        const int oc = oc0 + o;
#pragma unroll
        for (int py = 0; py < PY; py++) {
            const int gy = by0 + y0 + py;
            const size_t base = (((size_t)oc * H_IMG) + gy) * W_IMG + bx0 + x0;
            const int4 m = *reinterpret_cast<const int4*>(mask + base);
            float a0, a1, a2, a3;
            unpack2(acc[o][py][0], a0, a1);
            unpack2(acc[o][py][1], a2, a3);
            float4 v;
            float t;
            t = fmaf(a0, sc, sh); t = (t >= 0.0f) ? t : 0.01f * t; v.x = t * (float)m.x;
            t = fmaf(a1, sc, sh); t = (t >= 0.0f) ? t : 0.01f * t; v.y = t * (float)m.y;
            t = fmaf(a2, sc, sh); t = (t >= 0.0f) ? t : 0.01f * t; v.z = t * (float)m.z;
            t = fmaf(a3, sc, sh); t = (t >= 0.0f) ? t : 0.01f * t; v.w = t * (float)m.w;
            *reinterpret_cast<float4*>(out + base) = v;
        }
    }
}

extern "C" void kernel_launch(void* const* d_in, const int* in_sizes, int n_in,
                              void* d_out, int out_size) {
    const float* x     = (const float*)d_in[0];
    const float* wgt   = (const float*)d_in[1];
    const float* gamma = (const float*)d_in[2];
    const float* beta  = (const float*)d_in[3];
    const float* mean  = (const float*)d_in[4];
    const float* var   = (const float*)d_in[5];
    const int*   mask  = (const int*)d_in[6];
    float* out = (float*)d_out;

    dim3 block(NTH, 1, 1);
    dim3 grid(W_IMG / BX, H_IMG / BY, COUT / BOC);  // 4096 CTAs
    conv_bn_lrelu_mask_kernel<<<grid, block>>>(x, wgt, gamma, beta, mean, var, mask, out);
}

// round 6
// speedup vs baseline: 2.3477x; 2.3436x over previous
#include <cuda_runtime.h>
#include <cuda_bf16.h>
#include <cstdint>

// Fused 3x3 conv (reflect pad, 64->128ch, 512x512) + BN + LeakyReLU + mask via
// warp-level mma.sync (bf16 hi/lo split, 3 terms) implicit GEMM.
// 9 taps = 9 shifted GEMMs over one staged halo tile.

#define H_IMG 512
#define W_IMG 512
#define HP 514
#define WP 514
#define CIN 64
#define COUT 128
#define NTHR 256

// ---------------- device scratch ----------------
__device__ __align__(1024) unsigned char g_xh[(size_t)HP * WP * 128];  // [yy][xp][64ci] bf16 hi, 16B-chunks swizzled by xp&7
__device__ __align__(1024) unsigned char g_xl[(size_t)HP * WP * 128];  // lo
__device__ __align__(1024) unsigned char g_bwh[9 * 128 * 128];         // [tap][oc][64ci] bf16 hi, swizzled by oc&7
__device__ __align__(1024) unsigned char g_bwl[9 * 128 * 128];

// ---------------- helpers ----------------
__device__ __forceinline__ uint32_t smem_u32(const void* p) {
    uint32_t a;
    asm("{ .reg .u64 t; cvta.to.shared.u64 t, %1; cvt.u32.u64 %0, t; }" : "=r"(a) : "l"(p));
    return a;
}
__device__ __forceinline__ void cp_async16(uint32_t dst, const void* src) {
    asm volatile("cp.async.cg.shared.global [%0], [%1], 16;" :: "r"(dst), "l"(src));
}
__device__ __forceinline__ void cp_commit() { asm volatile("cp.async.commit_group;"); }
__device__ __forceinline__ void cp_wait0() { asm volatile("cp.async.wait_group 0;" ::: "memory"); }

__device__ __forceinline__ void ldsm4(uint32_t* r, uint32_t addr) {
    asm volatile("ldmatrix.sync.aligned.m8n8.x4.shared.b16 {%0,%1,%2,%3}, [%4];"
        : "=r"(r[0]), "=r"(r[1]), "=r"(r[2]), "=r"(r[3]) : "r"(addr));
}
__device__ __forceinline__ void mma16816(float* d, const uint32_t* a, uint32_t b0, uint32_t b1) {
    asm volatile(
        "mma.sync.aligned.m16n8k16.row.col.f32.bf16.bf16.f32 "
        "{%0,%1,%2,%3}, {%4,%5,%6,%7}, {%8,%9}, {%0,%1,%2,%3};"
        : "+f"(d[0]), "+f"(d[1]), "+f"(d[2]), "+f"(d[3])
        : "r"(a[0]), "r"(a[1]), "r"(a[2]), "r"(a[3]), "r"(b0), "r"(b1));
}

// ---------------- prep kernels ----------------
__global__ void prep_x_kernel(const float* __restrict__ x) {
    int idx = blockIdx.x * blockDim.x + threadIdx.x;
    if (idx >= HP * WP) return;
    const int yy = idx / WP, xp = idx % WP;
    int sy = yy - 1; sy = (sy < 0) ? 1 : ((sy > H_IMG - 1) ? (H_IMG - 2) : sy);
    int sx = xp - 1; sx = (sx < 0) ? 1 : ((sx > W_IMG - 1) ? (W_IMG - 2) : sx);
    const float* src = x + (size_t)sy * W_IMG + sx;
    uint4* oh = (uint4*)(g_xh + (size_t)idx * 128);
    uint4* ol = (uint4*)(g_xl + (size_t)idx * 128);
    const int sw = xp & 7;
#pragma unroll
    for (int chunk = 0; chunk < 8; chunk++) {
        const int cig = chunk ^ sw;   // smem/gmem chunk `chunk` holds ci-group chunk^sw
        uint32_t h[4], l[4];
#pragma unroll
        for (int j = 0; j < 4; j++) {
            const float a = src[(size_t)(cig * 8 + 2 * j) * (H_IMG * W_IMG)];
            const float b = src[(size_t)(cig * 8 + 2 * j + 1) * (H_IMG * W_IMG)];
            const __nv_bfloat16 ah = __float2bfloat16(a);
            const __nv_bfloat16 bh = __float2bfloat16(b);
            const __nv_bfloat16 al = __float2bfloat16(a - __bfloat162float(ah));
            const __nv_bfloat16 bl = __float2bfloat16(b - __bfloat162float(bh));
            h[j] = (uint32_t)__bfloat16_as_ushort(ah) | ((uint32_t)__bfloat16_as_ushort(bh) << 16);
            l[j] = (uint32_t)__bfloat16_as_ushort(al) | ((uint32_t)__bfloat16_as_ushort(bl) << 16);
        }
        oh[chunk] = make_uint4(h[0], h[1], h[2], h[3]);
        ol[chunk] = make_uint4(l[0], l[1], l[2], l[3]);
    }
}

__global__ void prep_w_kernel(const float* __restrict__ wgt) {  // [128oc][64ci][3][3]
    int idx = blockIdx.x * blockDim.x + threadIdx.x;
    if (idx >= 9 * 128) return;
    const int t = idx / 128, n = idx % 128;
    uint4* oh = (uint4*)(g_bwh + ((size_t)t * 128 + n) * 128);
    uint4* ol = (uint4*)(g_bwl + ((size_t)t * 128 + n) * 128);
    const int sw = n & 7;
#pragma unroll
    for (int chunk = 0; chunk < 8; chunk++) {
        const int cig = chunk ^ sw;
        uint32_t h[4], l[4];
#pragma unroll
        for (int j = 0; j < 4; j++) {
            const float a = wgt[(size_t)n * 576 + (cig * 8 + 2 * j) * 9 + t];
            const float b = wgt[(size_t)n * 576 + (cig * 8 + 2 * j + 1) * 9 + t];
            const __nv_bfloat16 ah = __float2bfloat16(a);
            const __nv_bfloat16 bh = __float2bfloat16(b);
            const __nv_bfloat16 al = __float2bfloat16(a - __bfloat162float(ah));
            const __nv_bfloat16 bl = __float2bfloat16(b - __bfloat162float(bh));
            h[j] = (uint32_t)__bfloat16_as_ushort(ah) | ((uint32_t)__bfloat16_as_ushort(bh) << 16);
            l[j] = (uint32_t)__bfloat16_as_ushort(al) | ((uint32_t)__bfloat16_as_ushort(bl) << 16);
        }
        oh[chunk] = make_uint4(h[0], h[1], h[2], h[3]);
        ol[chunk] = make_uint4(l[0], l[1], l[2], l[3]);
    }
}

// ---------------- main MMA kernel ----------------
// SMEM (bytes, relative to dynamic smem base):
//  A hi:   [0,      49920)   3 dy-rows x 130 px x 128B
//  A lo:   [49920,  99840)
//  B:      [99840, 165376)   4 x 16KB: buf0{hi,lo}, buf1{hi,lo}
//  scale:  [165376, 165888)
//  shift:  [165888, 166400)
//  C stage (reuses A region): 128 oc x 132 floats = 67584 B
#define OFF_AH 0
#define OFF_AL 49920
#define OFF_B  99840
#define OFF_SCALE 165376
#define OFF_SHIFT 165888
#define SMEM_NEED 166400
#define CSTR 132

__global__ void __launch_bounds__(NTHR) conv_mma_kernel(
    const float* __restrict__ gamma, const float* __restrict__ beta,
    const float* __restrict__ mean, const float* __restrict__ var,
    const int* __restrict__ mask, float* __restrict__ out) {
    extern __shared__ __align__(128) char sgen[];
    const uint32_t sb = smem_u32(sgen);
    float* s_scale = (float*)(sgen + OFF_SCALE);
    float* s_shift = (float*)(sgen + OFF_SHIFT);

    const int tid = threadIdx.x;
    const int wid = tid >> 5, lid = tid & 31;
    const int warpM = wid & 1;        // 2 warps over px (64 each)
    const int warpN = wid >> 1;       // 4 warps over oc (32 each)
    const int y = blockIdx.x >> 2;
    const int x0 = (blockIdx.x & 3) << 7;

    if (tid < COUT) {
        const float inv = rsqrtf(var[tid] + 1e-5f);
        const float sc = gamma[tid] * inv;
        s_scale[tid] = sc;
        s_shift[tid] = beta[tid] - mean[tid] * sc;
    }

    // ---- stage A halo (hi+lo, 3 dy-rows x 130 px), rows pre-swizzled in gmem ----
    for (int rid = tid; rid < 2 * 3 * 130; rid += NTHR) {
        const int p = rid / 390, rem = rid % 390;
        const int dy = rem / 130, pxl = rem % 130;
        const unsigned char* src = (p ? g_xl : g_xh) + ((size_t)((y + dy) * WP + (x0 + pxl))) * 128;
        const uint32_t dst = sb + (p ? OFF_AL : OFF_AH) + (uint32_t)(dy * 130 + pxl) * 128;
#pragma unroll
        for (int c = 0; c < 8; c++) cp_async16(dst + c * 16, src + c * 16);
    }
    // ---- stage B tap 0 into buf 0 ----
    for (int i = tid; i < 2 * 1024; i += NTHR) {
        const int hl = i >> 10, c = i & 1023;
        const unsigned char* src = (hl ? g_bwl : g_bwh) + (size_t)c * 16;
        cp_async16(sb + OFF_B + hl * 16384 + c * 16, src);
    }
    cp_commit();
    cp_wait0();
    __syncthreads();

    float acc[4][4][4];
#pragma unroll
    for (int mf = 0; mf < 4; mf++)
#pragma unroll
        for (int nf = 0; nf < 4; nf++)
#pragma unroll
            for (int e = 0; e < 4; e++) acc[mf][nf][e] = 0.0f;

    // per-lane ldmatrix address components
    const int a_rowpart = (lid & 7) + ((lid >> 3) & 1) * 8;  // m within 16
    const int a_cs = (lid >> 4) & 1;                          // k-chunk select
    const int b_rowpart = (lid & 7) + ((lid >> 4) & 1) * 8;  // n within 16
    const int b_cs = (lid >> 3) & 1;
    const int b_swz = lid & 7;
    // B row addresses are tap-invariant
    uint32_t b_addr0[2], b_addr1[2];  // [nfp] hi/lo filled per buf below

    for (int t = 0; t < 9; t++) {
        const int dy = t / 3, dx = t % 3;
        const int buf = t & 1;

        if (t < 8) {  // prefetch next tap into other buf
            const int nb = (t + 1) & 1;
            for (int i = tid; i < 2 * 1024; i += NTHR) {
                const int hl = i >> 10, c = i & 1023;
                const unsigned char* src = (hl ? g_bwl : g_bwh) + ((size_t)(t + 1) * 16384) + (size_t)c * 16;
                cp_async16(sb + OFF_B + (nb * 2 + hl) * 16384 + c * 16, src);
            }
            cp_commit();
        }

        // tap-constant pieces
        const int pixbase = warpM * 64 + dx + a_rowpart;
        const int a_swz = (a_rowpart + dx) & 7;
        const uint32_t a_row_h = sb + OFF_AH + (uint32_t)(dy * 130 + pixbase) * 128;
        const uint32_t a_row_l = sb + OFF_AL + (uint32_t)(dy * 130 + pixbase) * 128;
        const uint32_t b_base_h = sb + OFF_B + (buf * 2 + 0) * 16384;
        const uint32_t b_base_l = sb + OFF_B + (buf * 2 + 1) * 16384;
#pragma unroll
        for (int nfp = 0; nfp < 2; nfp++) {
            const uint32_t nrow = (uint32_t)(warpN * 32 + nfp * 16 + b_rowpart) * 128;
            b_addr0[nfp] = b_base_h + nrow;
            b_addr1[nfp] = b_base_l + nrow;
        }

#pragma unroll
        for (int ks = 0; ks < 4; ks++) {
            uint32_t bh[8], bl[8];
            const uint32_t bco = (uint32_t)(((ks * 2 + b_cs) ^ b_swz) << 4);
            ldsm4(bh + 0, b_addr0[0] + bco);
            ldsm4(bh + 4, b_addr0[1] + bco);
            ldsm4(bl + 0, b_addr1[0] + bco);
            ldsm4(bl + 4, b_addr1[1] + bco);
            const uint32_t aco = (uint32_t)(((ks * 2 + a_cs) ^ a_swz) << 4);
#pragma unroll
            for (int mf = 0; mf < 4; mf++) {
                uint32_t ah[4], al[4];
                ldsm4(ah, a_row_h + (uint32_t)mf * 2048 + aco);
                ldsm4(al, a_row_l + (uint32_t)mf * 2048 + aco);
#pragma unroll
                for (int nf = 0; nf < 4; nf++) {
                    mma16816(acc[mf][nf], ah, bh[nf * 2], bh[nf * 2 + 1]);
                    mma16816(acc[mf][nf], ah, bl[nf * 2], bl[nf * 2 + 1]);
                    mma16816(acc[mf][nf], al, bh[nf * 2], bh[nf * 2 + 1]);
                }
            }
        }

        if (t < 8) {
            cp_wait0();
            __syncthreads();
        }
    }

    __syncthreads();  // done reading A everywhere before C staging reuses it

    // ---- stage C = [oc][px] fp32 in smem (padded rows), then coalesced epilogue ----
    float* C = (float*)sgen;  // reuses A region: 128*132*4 = 67584 B
#pragma unroll
    for (int mf = 0; mf < 4; mf++) {
        const int m0 = warpM * 64 + mf * 16 + (lid >> 2);
#pragma unroll
        for (int nf = 0; nf < 4; nf++) {
            const int oc = warpN * 32 + nf * 8 + (lid & 3) * 2;
            C[oc * CSTR + m0]           = acc[mf][nf][0];
            C[(oc + 1) * CSTR + m0]     = acc[mf][nf][1];
            C[oc * CSTR + m0 + 8]       = acc[mf][nf][2];
            C[(oc + 1) * CSTR + m0 + 8] = acc[mf][nf][3];
        }
    }
    __syncthreads();

    for (int q = tid; q < 128 * 32; q += NTHR) {
        const int oc = q >> 5;
        const int px = (q & 31) * 4;
        const float4 v = *(const float4*)(C + oc * CSTR + px);
        const float sc = s_scale[oc], sh = s_shift[oc];
        const size_t gidx = (size_t)oc * (H_IMG * W_IMG) + (size_t)y * W_IMG + x0 + px;
        const int4 m = *(const int4*)(mask + gidx);
        float4 r;
        float tv;
        tv = v.x * sc + sh; tv = (tv >= 0.0f) ? tv : 0.01f * tv; r.x = tv * (float)m.x;
        tv = v.y * sc + sh; tv = (tv >= 0.0f) ? tv : 0.01f * tv; r.y = tv * (float)m.y;
        tv = v.z * sc + sh; tv = (tv >= 0.0f) ? tv : 0.01f * tv; r.z = tv * (float)m.z;
        tv = v.w * sc + sh; tv = (tv >= 0.0f) ? tv : 0.01f * tv; r.w = tv * (float)m.w;
        *(float4*)(out + gidx) = r;
    }
}

// ---------------- host launch ----------------
extern "C" void kernel_launch(void* const* d_in, const int* in_sizes, int n_in,
                              void* d_out, int out_size) {
    const float* x     = (const float*)d_in[0];
    const float* wgt   = (const float*)d_in[1];
    const float* gamma = (const float*)d_in[2];
    const float* beta  = (const float*)d_in[3];
    const float* mean  = (const float*)d_in[4];
    const float* var   = (const float*)d_in[5];
    const int*   mask  = (const int*)d_in[6];
    float* out = (float*)d_out;

    cudaFuncSetAttribute(conv_mma_kernel, cudaFuncAttributeMaxDynamicSharedMemorySize, SMEM_NEED);

    prep_w_kernel<<<(9 * 128 + 127) / 128, 128>>>(wgt);
    prep_x_kernel<<<(HP * WP + 255) / 256, 256>>>(x);
    conv_mma_kernel<<<2048, NTHR, SMEM_NEED>>>(gamma, beta, mean, var, mask, out);
}

// round 10
// speedup vs baseline: 2.9311x; 1.2485x over previous
#include <cuda_runtime.h>
#include <cuda_bf16.h>
#include <cstdint>

// Fused 3x3 conv (reflect pad, 64->128ch, 512x512) + BN + LeakyReLU + mask via
// warp-level mma.sync (bf16 hi/lo split, 3 terms) implicit GEMM.
// R9 = R7 resubmit (infra failure, never measured): 2 output rows per CTA
// (m=256, n=128), grid 1024; better A/B reuse, 6:1 MMA:LDSM.

#define H_IMG 512
#define W_IMG 512
#define HP 514
#define WP 514
#define CIN 64
#define COUT 128
#define NTHR 256

// ---------------- device scratch ----------------
__device__ __align__(1024) unsigned char g_xh[(size_t)HP * WP * 128];  // [yy][xp][64ci] bf16 hi, 16B chunks swizzled by xp&7
__device__ __align__(1024) unsigned char g_xl[(size_t)HP * WP * 128];  // lo
__device__ __align__(1024) unsigned char g_bwh[9 * 128 * 128];         // [tap][oc][64ci] bf16 hi, swizzled by oc&7
__device__ __align__(1024) unsigned char g_bwl[9 * 128 * 128];

// ---------------- helpers ----------------
__device__ __forceinline__ uint32_t smem_u32(const void* p) {
    uint32_t a;
    asm("{ .reg .u64 t; cvta.to.shared.u64 t, %1; cvt.u32.u64 %0, t; }" : "=r"(a) : "l"(p));
    return a;
}
__device__ __forceinline__ void cp_async16(uint32_t dst, const void* src) {
    asm volatile("cp.async.cg.shared.global [%0], [%1], 16;" :: "r"(dst), "l"(src));
}
__device__ __forceinline__ void cp_commit() { asm volatile("cp.async.commit_group;"); }
__device__ __forceinline__ void cp_wait0() { asm volatile("cp.async.wait_group 0;" ::: "memory"); }

__device__ __forceinline__ void ldsm4(uint32_t* r, uint32_t addr) {
    asm volatile("ldmatrix.sync.aligned.m8n8.x4.shared.b16 {%0,%1,%2,%3}, [%4];"
        : "=r"(r[0]), "=r"(r[1]), "=r"(r[2]), "=r"(r[3]) : "r"(addr));
}
__device__ __forceinline__ void mma16816(float* d, const uint32_t* a, uint32_t b0, uint32_t b1) {
    asm volatile(
        "mma.sync.aligned.m16n8k16.row.col.f32.bf16.bf16.f32 "
        "{%0,%1,%2,%3}, {%4,%5,%6,%7}, {%8,%9}, {%0,%1,%2,%3};"
        : "+f"(d[0]), "+f"(d[1]), "+f"(d[2]), "+f"(d[3])
        : "r"(a[0]), "r"(a[1]), "r"(a[2]), "r"(a[3]), "r"(b0), "r"(b1));
}

// ---------------- prep kernels ----------------
__global__ void prep_x_kernel(const float* __restrict__ x) {
    int idx = blockIdx.x * blockDim.x + threadIdx.x;
    if (idx >= HP * WP) return;
    const int yy = idx / WP, xp = idx % WP;
    int sy = yy - 1; sy = (sy < 0) ? 1 : ((sy > H_IMG - 1) ? (H_IMG - 2) : sy);
    int sx = xp - 1; sx = (sx < 0) ? 1 : ((sx > W_IMG - 1) ? (W_IMG - 2) : sx);
    const float* src = x + (size_t)sy * W_IMG + sx;
    uint4* oh = (uint4*)(g_xh + (size_t)idx * 128);
    uint4* ol = (uint4*)(g_xl + (size_t)idx * 128);
    const int sw = xp & 7;
#pragma unroll
    for (int chunk = 0; chunk < 8; chunk++) {
        const int cig = chunk ^ sw;
        uint32_t h[4], l[4];
#pragma unroll
        for (int j = 0; j < 4; j++) {
            const float a = src[(size_t)(cig * 8 + 2 * j) * (H_IMG * W_IMG)];
            const float b = src[(size_t)(cig * 8 + 2 * j + 1) * (H_IMG * W_IMG)];
            const __nv_bfloat16 ah = __float2bfloat16(a);
            const __nv_bfloat16 bh = __float2bfloat16(b);
            const __nv_bfloat16 al = __float2bfloat16(a - __bfloat162float(ah));
            const __nv_bfloat16 bl = __float2bfloat16(b - __bfloat162float(bh));
            h[j] = (uint32_t)__bfloat16_as_ushort(ah) | ((uint32_t)__bfloat16_as_ushort(bh) << 16);
            l[j] = (uint32_t)__bfloat16_as_ushort(al) | ((uint32_t)__bfloat16_as_ushort(bl) << 16);
        }
        oh[chunk] = make_uint4(h[0], h[1], h[2], h[3]);
        ol[chunk] = make_uint4(l[0], l[1], l[2], l[3]);
    }
}

__global__ void prep_w_kernel(const float* __restrict__ wgt) {  // [128oc][64ci][3][3]
    int idx = blockIdx.x * blockDim.x + threadIdx.x;   // (t, n, chunk)
    if (idx >= 9 * 128 * 8) return;
    const int chunk = idx & 7;
    const int n = (idx >> 3) & 127;
    const int t = idx >> 10;
    uint4* oh = (uint4*)(g_bwh + ((size_t)t * 128 + n) * 128) + chunk;
    uint4* ol = (uint4*)(g_bwl + ((size_t)t * 128 + n) * 128) + chunk;
    const int cig = chunk ^ (n & 7);
    uint32_t h[4], l[4];
#pragma unroll
    for (int j = 0; j < 4; j++) {
        const float a = wgt[(size_t)n * 576 + (cig * 8 + 2 * j) * 9 + t];
        const float b = wgt[(size_t)n * 576 + (cig * 8 + 2 * j + 1) * 9 + t];
        const __nv_bfloat16 ah = __float2bfloat16(a);
        const __nv_bfloat16 bh = __float2bfloat16(b);
        const __nv_bfloat16 al = __float2bfloat16(a - __bfloat162float(ah));
        const __nv_bfloat16 bl = __float2bfloat16(b - __bfloat162float(bh));
        h[j] = (uint32_t)__bfloat16_as_ushort(ah) | ((uint32_t)__bfloat16_as_ushort(bh) << 16);
        l[j] = (uint32_t)__bfloat16_as_ushort(al) | ((uint32_t)__bfloat16_as_ushort(bl) << 16);
    }
    *oh = make_uint4(h[0], h[1], h[2], h[3]);
    *ol = make_uint4(l[0], l[1], l[2], l[3]);
}

// ---------------- main MMA kernel ----------------
// SMEM:
//  A hi:  [0,      66560)   4 dy-rows x 130 px x 128B
//  A lo:  [66560, 133120)
//  B:     [133120, 198656)  4 x 16KB: buf0{hi,lo}, buf1{hi,lo}
//  scale: [198656, 199168)
//  shift: [199168, 199680)
//  C stage (reuses A): 128 oc x 260 floats = 133120 B
#define OFF_AH 0
#define OFF_AL 66560
#define OFF_B  133120
#define OFF_SCALE 198656
#define OFF_SHIFT 199168
#define SMEM_NEED 199680
#define CSTR 260

__global__ void __launch_bounds__(NTHR, 1) conv_mma_kernel(
    const float* __restrict__ gamma, const float* __restrict__ beta,
    const float* __restrict__ mean, const float* __restrict__ var,
    const int* __restrict__ mask, float* __restrict__ out) {
    extern __shared__ __align__(128) char sgen[];
    const uint32_t sb = smem_u32(sgen);
    float* s_scale = (float*)(sgen + OFF_SCALE);
    float* s_shift = (float*)(sgen + OFF_SHIFT);

    const int tid = threadIdx.x;
    const int wid = tid >> 5, lid = tid & 31;
    const int warpM = wid & 3;        // 4 m-frag groups (64 px each over 2 rows)
    const int warpN = wid >> 2;       // 2 n-groups (64 oc each)
    const int rowSel = warpM >> 1;    // which of the 2 output rows
    const int px0 = (warpM & 1) * 64;
    const int y0 = (blockIdx.x >> 2) * 2;
    const int x0 = (blockIdx.x & 3) << 7;

    if (tid < COUT) {
        const float inv = rsqrtf(var[tid] + 1e-5f);
        const float sc = gamma[tid] * inv;
        s_scale[tid] = sc;
        s_shift[tid] = beta[tid] - mean[tid] * sc;
    }

    // ---- stage A halo: hi+lo, 4 dy-rows x 130 px (rows pre-swizzled in gmem) ----
    for (int rid = tid; rid < 2 * 4 * 130; rid += NTHR) {
        const int p = rid / 520, rem = rid % 520;
        const int dy = rem / 130, pxl = rem % 130;
        const unsigned char* src = (p ? g_xl : g_xh) + ((size_t)((y0 + dy) * WP + (x0 + pxl))) * 128;
        const uint32_t dst = sb + (p ? OFF_AL : OFF_AH) + (uint32_t)(dy * 130 + pxl) * 128;
#pragma unroll
        for (int c = 0; c < 8; c++) cp_async16(dst + c * 16, src + c * 16);
    }
    // ---- stage B tap 0 into buf 0 ----
    for (int i = tid; i < 2 * 1024; i += NTHR) {
        const int hl = i >> 10, c = i & 1023;
        const unsigned char* src = (hl ? g_bwl : g_bwh) + (size_t)c * 16;
        cp_async16(sb + OFF_B + hl * 16384 + c * 16, src);
    }
    cp_commit();
    cp_wait0();
    __syncthreads();

    float acc[4][8][4];
#pragma unroll
    for (int mf = 0; mf < 4; mf++)
#pragma unroll
        for (int nf = 0; nf < 8; nf++)
#pragma unroll
            for (int e = 0; e < 4; e++) acc[mf][nf][e] = 0.0f;

    const int a_rowpart = (lid & 7) + ((lid >> 3) & 1) * 8;
    const int a_cs = (lid >> 4) & 1;
    const int b_rowpart = (lid & 7) + ((lid >> 4) & 1) * 8;
    const int b_cs = (lid >> 3) & 1;
    const int b_swz = lid & 7;

    for (int t = 0; t < 9; t++) {
        const int dy = t / 3, dx = t % 3;
        const int buf = t & 1;

        if (t < 8) {
            const int nb = (t + 1) & 1;
            for (int i = tid; i < 2 * 1024; i += NTHR) {
                const int hl = i >> 10, c = i & 1023;
                const unsigned char* src = (hl ? g_bwl : g_bwh) + ((size_t)(t + 1) * 16384) + (size_t)c * 16;
                cp_async16(sb + OFF_B + (nb * 2 + hl) * 16384 + c * 16, src);
            }
            cp_commit();
        }

        const int pixbase = px0 + dx + a_rowpart;
        const int a_swz = (a_rowpart + dx) & 7;   // (px0 + ...) & 7, px0 % 8 == 0
        const uint32_t a_row_h = sb + OFF_AH + (uint32_t)((dy + rowSel) * 130 + pixbase) * 128;
        const uint32_t a_row_l = sb + OFF_AL + (uint32_t)((dy + rowSel) * 130 + pixbase) * 128;
        const uint32_t b_base_h = sb + OFF_B + (buf * 2 + 0) * 16384;
        const uint32_t b_base_l = sb + OFF_B + (buf * 2 + 1) * 16384;
        uint32_t b_addr_h[4], b_addr_l[4];
#pragma unroll
        for (int nfp = 0; nfp < 4; nfp++) {
            const uint32_t nrow = (uint32_t)(warpN * 64 + nfp * 16 + b_rowpart) * 128;
            b_addr_h[nfp] = b_base_h + nrow;
            b_addr_l[nfp] = b_base_l + nrow;
        }

#pragma unroll
        for (int ks = 0; ks < 4; ks++) {
            uint32_t bh[16], bl[16];
            const uint32_t bco = (uint32_t)(((ks * 2 + b_cs) ^ b_swz) << 4);
#pragma unroll
            for (int nfp = 0; nfp < 4; nfp++) {
                ldsm4(bh + nfp * 4, b_addr_h[nfp] + bco);
                ldsm4(bl + nfp * 4, b_addr_l[nfp] + bco);
            }
            const uint32_t aco = (uint32_t)(((ks * 2 + a_cs) ^ a_swz) << 4);
#pragma unroll
            for (int mf = 0; mf < 4; mf++) {
                uint32_t ah[4], al[4];
                ldsm4(ah, a_row_h + (uint32_t)mf * 2048 + aco);
                ldsm4(al, a_row_l + (uint32_t)mf * 2048 + aco);
#pragma unroll
                for (int nf = 0; nf < 8; nf++) {
                    mma16816(acc[mf][nf], ah, bh[nf * 2], bh[nf * 2 + 1]);
                    mma16816(acc[mf][nf], ah, bl[nf * 2], bl[nf * 2 + 1]);
                    mma16816(acc[mf][nf], al, bh[nf * 2], bh[nf * 2 + 1]);
                }
            }
        }

        if (t < 8) {
            cp_wait0();
            __syncthreads();
        }
    }

    __syncthreads();  // all warps done reading A before C staging reuses it

    // ---- stage C = [oc][m 256] fp32 in smem, then coalesced epilogue ----
    float* C = (float*)sgen;  // 128 * 260 * 4 = 133120 B (A region)
#pragma unroll
    for (int mf = 0; mf < 4; mf++) {
        const int m0 = rowSel * 128 + px0 + mf * 16 + (lid >> 2);
#pragma unroll
        for (int nf = 0; nf < 8; nf++) {
            const int oc = warpN * 64 + nf * 8 + (lid & 3) * 2;
            C[oc * CSTR + m0]           = acc[mf][nf][0];
            C[(oc + 1) * CSTR + m0]     = acc[mf][nf][1];
            C[oc * CSTR + m0 + 8]       = acc[mf][nf][2];
            C[(oc + 1) * CSTR + m0 + 8] = acc[mf][nf][3];
        }
    }
    __syncthreads();

    for (int q = tid; q < 128 * 64; q += NTHR) {
        const int oc = q >> 6;
        const int pxq = (q & 63) * 4;
        const int row = pxq >> 7;               // 0 or 1
        const int xq = pxq & 127;
        const float4 v = *(const float4*)(C + oc * CSTR + pxq);
        const float sc = s_scale[oc], sh = s_shift[oc];
        const size_t gidx = (size_t)oc * (H_IMG * W_IMG) + (size_t)(y0 + row) * W_IMG + x0 + xq;
        const int4 m = *(const int4*)(mask + gidx);
        float4 r;
        float tv;
        tv = v.x * sc + sh; tv = (tv >= 0.0f) ? tv : 0.01f * tv; r.x = tv * (float)m.x;
        tv = v.y * sc + sh; tv = (tv >= 0.0f) ? tv : 0.01f * tv; r.y = tv * (float)m.y;
        tv = v.z * sc + sh; tv = (tv >= 0.0f) ? tv : 0.01f * tv; r.z = tv * (float)m.z;
        tv = v.w * sc + sh; tv = (tv >= 0.0f) ? tv : 0.01f * tv; r.w = tv * (float)m.w;
        *(float4*)(out + gidx) = r;
    }
}

// ---------------- host launch ----------------
extern "C" void kernel_launch(void* const* d_in, const int* in_sizes, int n_in,
                              void* d_out, int out_size) {
    const float* x     = (const float*)d_in[0];
    const float* wgt   = (const float*)d_in[1];
    const float* gamma = (const float*)d_in[2];
    const float* beta  = (const float*)d_in[3];
    const float* mean  = (const float*)d_in[4];
    const float* var   = (const float*)d_in[5];
    const int*   mask  = (const int*)d_in[6];
    float* out = (float*)d_out;

    cudaFuncSetAttribute(conv_mma_kernel, cudaFuncAttributeMaxDynamicSharedMemorySize, SMEM_NEED);

    prep_w_kernel<<<(9 * 128 * 8 + 127) / 128, 128>>>(wgt);
    prep_x_kernel<<<(HP * WP + 255) / 256, 256>>>(x);
    conv_mma_kernel<<<1024, NTHR, SMEM_NEED>>>(gamma, beta, mean, var, mask, out);
}

// round 11
// speedup vs baseline: 3.6095x; 1.2314x over previous
#include <cuda_runtime.h>
#include <cuda_fp16.h>
#include <cstdint>

// Fused 3x3 conv (reflect pad, 64->128ch, 512x512) + BN + LeakyReLU + mask via
// warp-level mma.sync implicit GEMM.
// R11: fp16 2-term split (x = Ah + Al, w ~= Bh):  D = Ah*Bh + Al*Bh.
// 2/3 the MMA count of the bf16 3-term scheme; B smem traffic halved.

#define H_IMG 512
#define W_IMG 512
#define HP 514
#define WP 514
#define CIN 64
#define COUT 128
#define NTHR 256

// ---------------- device scratch ----------------
__device__ __align__(1024) unsigned char g_xh[(size_t)HP * WP * 128];  // [yy][xp][64ci] fp16 hi, 16B chunks swizzled by xp&7
__device__ __align__(1024) unsigned char g_xl[(size_t)HP * WP * 128];  // fp16 residual
__device__ __align__(1024) unsigned char g_bwh[9 * 128 * 128];         // [tap][oc][64ci] fp16, swizzled by oc&7

// ---------------- helpers ----------------
__device__ __forceinline__ uint32_t smem_u32(const void* p) {
    uint32_t a;
    asm("{ .reg .u64 t; cvta.to.shared.u64 t, %1; cvt.u32.u64 %0, t; }" : "=r"(a) : "l"(p));
    return a;
}
__device__ __forceinline__ void cp_async16(uint32_t dst, const void* src) {
    asm volatile("cp.async.cg.shared.global [%0], [%1], 16;" :: "r"(dst), "l"(src));
}
__device__ __forceinline__ void cp_commit() { asm volatile("cp.async.commit_group;"); }
__device__ __forceinline__ void cp_wait0() { asm volatile("cp.async.wait_group 0;" ::: "memory"); }

__device__ __forceinline__ void ldsm4(uint32_t* r, uint32_t addr) {
    asm volatile("ldmatrix.sync.aligned.m8n8.x4.shared.b16 {%0,%1,%2,%3}, [%4];"
        : "=r"(r[0]), "=r"(r[1]), "=r"(r[2]), "=r"(r[3]) : "r"(addr));
}
__device__ __forceinline__ void mma16816(float* d, const uint32_t* a, uint32_t b0, uint32_t b1) {
    asm volatile(
        "mma.sync.aligned.m16n8k16.row.col.f32.f16.f16.f32 "
        "{%0,%1,%2,%3}, {%4,%5,%6,%7}, {%8,%9}, {%0,%1,%2,%3};"
        : "+f"(d[0]), "+f"(d[1]), "+f"(d[2]), "+f"(d[3])
        : "r"(a[0]), "r"(a[1]), "r"(a[2]), "r"(a[3]), "r"(b0), "r"(b1));
}

// ---------------- prep kernels ----------------
__global__ void prep_x_kernel(const float* __restrict__ x) {
    int idx = blockIdx.x * blockDim.x + threadIdx.x;
    if (idx >= HP * WP) return;
    const int yy = idx / WP, xp = idx % WP;
    int sy = yy - 1; sy = (sy < 0) ? 1 : ((sy > H_IMG - 1) ? (H_IMG - 2) : sy);
    int sx = xp - 1; sx = (sx < 0) ? 1 : ((sx > W_IMG - 1) ? (W_IMG - 2) : sx);
    const float* src = x + (size_t)sy * W_IMG + sx;
    uint4* oh = (uint4*)(g_xh + (size_t)idx * 128);
    uint4* ol = (uint4*)(g_xl + (size_t)idx * 128);
    const int sw = xp & 7;
#pragma unroll
    for (int chunk = 0; chunk < 8; chunk++) {
        const int cig = chunk ^ sw;
        uint32_t h[4], l[4];
#pragma unroll
        for (int j = 0; j < 4; j++) {
            const float a = src[(size_t)(cig * 8 + 2 * j) * (H_IMG * W_IMG)];
            const float b = src[(size_t)(cig * 8 + 2 * j + 1) * (H_IMG * W_IMG)];
            const __half ah = __float2half_rn(a);
            const __half bh = __float2half_rn(b);
            const __half al = __float2half_rn(a - __half2float(ah));
            const __half bl = __float2half_rn(b - __half2float(bh));
            h[j] = (uint32_t)__half_as_ushort(ah) | ((uint32_t)__half_as_ushort(bh) << 16);
            l[j] = (uint32_t)__half_as_ushort(al) | ((uint32_t)__half_as_ushort(bl) << 16);
        }
        oh[chunk] = make_uint4(h[0], h[1], h[2], h[3]);
        ol[chunk] = make_uint4(l[0], l[1], l[2], l[3]);
    }
}

__global__ void prep_w_kernel(const float* __restrict__ wgt) {  // [128oc][64ci][3][3]
    int idx = blockIdx.x * blockDim.x + threadIdx.x;   // (t, n, chunk)
    if (idx >= 9 * 128 * 8) return;
    const int chunk = idx & 7;
    const int n = (idx >> 3) & 127;
    const int t = idx >> 10;
    uint4* oh = (uint4*)(g_bwh + ((size_t)t * 128 + n) * 128) + chunk;
    const int cig = chunk ^ (n & 7);
    uint32_t h[4];
#pragma unroll
    for (int j = 0; j < 4; j++) {
        const float a = wgt[(size_t)n * 576 + (cig * 8 + 2 * j) * 9 + t];
        const float b = wgt[(size_t)n * 576 + (cig * 8 + 2 * j + 1) * 9 + t];
        h[j] = (uint32_t)__half_as_ushort(__float2half_rn(a)) |
               ((uint32_t)__half_as_ushort(__float2half_rn(b)) << 16);
    }
    *oh = make_uint4(h[0], h[1], h[2], h[3]);
}

// ---------------- main MMA kernel ----------------
// SMEM:
//  A hi:  [0,      66560)   4 dy-rows x 130 px x 128B
//  A lo:  [66560, 133120)
//  B:     [133120, 165888)  2 x 16KB double buffer (hi only)
//  scale: [165888, 166400)
//  shift: [166400, 166912)
//  C stage (reuses A): 128 oc x 260 floats = 133120 B
#define OFF_AH 0
#define OFF_AL 66560
#define OFF_B  133120
#define OFF_SCALE 165888
#define OFF_SHIFT 166400
#define SMEM_NEED 166912
#define CSTR 260

__global__ void __launch_bounds__(NTHR, 1) conv_mma_kernel(
    const float* __restrict__ gamma, const float* __restrict__ beta,
    const float* __restrict__ mean, const float* __restrict__ var,
    const int* __restrict__ mask, float* __restrict__ out) {
    extern __shared__ __align__(128) char sgen[];
    const uint32_t sb = smem_u32(sgen);
    float* s_scale = (float*)(sgen + OFF_SCALE);
    float* s_shift = (float*)(sgen + OFF_SHIFT);

    const int tid = threadIdx.x;
    const int wid = tid >> 5, lid = tid & 31;
    const int warpM = wid & 3;        // 4 m-frag groups (64 px each over 2 rows)
    const int warpN = wid >> 2;       // 2 n-groups (64 oc each)
    const int rowSel = warpM >> 1;
    const int px0 = (warpM & 1) * 64;
    const int y0 = (blockIdx.x >> 2) * 2;
    const int x0 = (blockIdx.x & 3) << 7;

    if (tid < COUT) {
        const float inv = rsqrtf(var[tid] + 1e-5f);
        const float sc = gamma[tid] * inv;
        s_scale[tid] = sc;
        s_shift[tid] = beta[tid] - mean[tid] * sc;
    }

    // ---- stage A halo: hi+lo, 4 dy-rows x 130 px (rows pre-swizzled in gmem) ----
    for (int rid = tid; rid < 2 * 4 * 130; rid += NTHR) {
        const int p = rid / 520, rem = rid % 520;
        const int dy = rem / 130, pxl = rem % 130;
        const unsigned char* src = (p ? g_xl : g_xh) + ((size_t)((y0 + dy) * WP + (x0 + pxl))) * 128;
        const uint32_t dst = sb + (p ? OFF_AL : OFF_AH) + (uint32_t)(dy * 130 + pxl) * 128;
#pragma unroll
        for (int c = 0; c < 8; c++) cp_async16(dst + c * 16, src + c * 16);
    }
    // ---- stage B tap 0 into buf 0 (hi only, 16KB) ----
    for (int i = tid; i < 1024; i += NTHR) {
        cp_async16(sb + OFF_B + i * 16, g_bwh + (size_t)i * 16);
    }
    cp_commit();
    cp_wait0();
    __syncthreads();

    float acc[4][8][4];
#pragma unroll
    for (int mf = 0; mf < 4; mf++)
#pragma unroll
        for (int nf = 0; nf < 8; nf++)
#pragma unroll
            for (int e = 0; e < 4; e++) acc[mf][nf][e] = 0.0f;

    const int a_rowpart = (lid & 7) + ((lid >> 3) & 1) * 8;
    const int a_cs = (lid >> 4) & 1;
    const int b_rowpart = (lid & 7) + ((lid >> 4) & 1) * 8;
    const int b_cs = (lid >> 3) & 1;
    const int b_swz = lid & 7;

    for (int t = 0; t < 9; t++) {
        const int dy = t / 3, dx = t % 3;
        const int buf = t & 1;

        if (t < 8) {
            const int nb = (t + 1) & 1;
            for (int i = tid; i < 1024; i += NTHR) {
                cp_async16(sb + OFF_B + nb * 16384 + i * 16,
                           g_bwh + ((size_t)(t + 1) * 16384) + (size_t)i * 16);
            }
            cp_commit();
        }

        const int pixbase = px0 + dx + a_rowpart;
        const int a_swz = (a_rowpart + dx) & 7;
        const uint32_t a_row_h = sb + OFF_AH + (uint32_t)((dy + rowSel) * 130 + pixbase) * 128;
        const uint32_t a_row_l = sb + OFF_AL + (uint32_t)((dy + rowSel) * 130 + pixbase) * 128;
        const uint32_t b_base = sb + OFF_B + buf * 16384;
        uint32_t b_addr[4];
#pragma unroll
        for (int nfp = 0; nfp < 4; nfp++) {
            b_addr[nfp] = b_base + (uint32_t)(warpN * 64 + nfp * 16 + b_rowpart) * 128;
        }

#pragma unroll
        for (int ks = 0; ks < 4; ks++) {
            uint32_t bh[16];
            const uint32_t bco = (uint32_t)(((ks * 2 + b_cs) ^ b_swz) << 4);
#pragma unroll
            for (int nfp = 0; nfp < 4; nfp++) {
                ldsm4(bh + nfp * 4, b_addr[nfp] + bco);
            }
            const uint32_t aco = (uint32_t)(((ks * 2 + a_cs) ^ a_swz) << 4);
#pragma unroll
            for (int mf = 0; mf < 4; mf++) {
                uint32_t ah[4], al[4];
                ldsm4(ah, a_row_h + (uint32_t)mf * 2048 + aco);
                ldsm4(al, a_row_l + (uint32_t)mf * 2048 + aco);
#pragma unroll
                for (int nf = 0; nf < 8; nf++) {
                    mma16816(acc[mf][nf], ah, bh[nf * 2], bh[nf * 2 + 1]);
                    mma16816(acc[mf][nf], al, bh[nf * 2], bh[nf * 2 + 1]);
                }
            }
        }

        if (t < 8) {
            cp_wait0();
            __syncthreads();
        }
    }

    __syncthreads();  // all warps done reading A before C staging reuses it

    // ---- stage C = [oc][m 256] fp32 in smem, then coalesced epilogue ----
    float* C = (float*)sgen;  // 128 * 260 * 4 = 133120 B (A region)
#pragma unroll
    for (int mf = 0; mf < 4; mf++) {
        const int m0 = rowSel * 128 + px0 + mf * 16 + (lid >> 2);
#pragma unroll
        for (int nf = 0; nf < 8; nf++) {
            const int oc = warpN * 64 + nf * 8 + (lid & 3) * 2;
            C[oc * CSTR + m0]           = acc[mf][nf][0];
            C[(oc + 1) * CSTR + m0]     = acc[mf][nf][1];
            C[oc * CSTR + m0 + 8]       = acc[mf][nf][2];
            C[(oc + 1) * CSTR + m0 + 8] = acc[mf][nf][3];
        }
    }
    __syncthreads();

    for (int q = tid; q < 128 * 64; q += NTHR) {
        const int oc = q >> 6;
        const int pxq = (q & 63) * 4;
        const int row = pxq >> 7;
        const int xq = pxq & 127;
        const float4 v = *(const float4*)(C + oc * CSTR + pxq);
        const float sc = s_scale[oc], sh = s_shift[oc];
        const size_t gidx = (size_t)oc * (H_IMG * W_IMG) + (size_t)(y0 + row) * W_IMG + x0 + xq;
        const int4 m = *(const int4*)(mask + gidx);
        float4 r;
        float tv;
        tv = v.x * sc + sh; tv = (tv >= 0.0f) ? tv : 0.01f * tv; r.x = tv * (float)m.x;
        tv = v.y * sc + sh; tv = (tv >= 0.0f) ? tv : 0.01f * tv; r.y = tv * (float)m.y;
        tv = v.z * sc + sh; tv = (tv >= 0.0f) ? tv : 0.01f * tv; r.z = tv * (float)m.z;
        tv = v.w * sc + sh; tv = (tv >= 0.0f) ? tv : 0.01f * tv; r.w = tv * (float)m.w;
        *(float4*)(out + gidx) = r;
    }
}

// ---------------- host launch ----------------
extern "C" void kernel_launch(void* const* d_in, const int* in_sizes, int n_in,
                              void* d_out, int out_size) {
    const float* x     = (const float*)d_in[0];
    const float* wgt   = (const float*)d_in[1];
    const float* gamma = (const float*)d_in[2];
    const float* beta  = (const float*)d_in[3];
    const float* mean  = (const float*)d_in[4];
    const float* var   = (const float*)d_in[5];
    const int*   mask  = (const int*)d_in[6];
    float* out = (float*)d_out;

    cudaFuncSetAttribute(conv_mma_kernel, cudaFuncAttributeMaxDynamicSharedMemorySize, SMEM_NEED);

    prep_w_kernel<<<(9 * 128 * 8 + 127) / 128, 128>>>(wgt);
    prep_x_kernel<<<(HP * WP + 255) / 256, 256>>>(x);
    conv_mma_kernel<<<1024, NTHR, SMEM_NEED>>>(gamma, beta, mean, var, mask, out);
}

// round 15
// speedup vs baseline: 5.0933x; 1.4111x over previous
#include <cuda_runtime.h>
#include <cuda_fp16.h>
#include <cstdint>

// Fused 3x3 conv (reflect pad, 64->128ch, 512x512) + BN + LeakyReLU + mask via
// warp-level mma.sync implicit GEMM.
// R15 = R12 with smem-layout fix: scale/shift moved PAST the C-stage region
// (R12 bug: C staging overwrote BN constants at 99328 before the epilogue read them).
// Pure fp16 single-term (x ~= Ah, w ~= Bh): D = Ah*Bh.

#define H_IMG 512
#define W_IMG 512
#define HP 514
#define WP 514
#define CIN 64
#define COUT 128
#define NTHR 256

// ---------------- device scratch ----------------
__device__ __align__(1024) unsigned char g_xh[(size_t)HP * WP * 128];  // [yy][xp][64ci] fp16, 16B chunks swizzled by xp&7
__device__ __align__(1024) unsigned char g_bwh[9 * 128 * 128];         // [tap][oc][64ci] fp16, swizzled by oc&7

// ---------------- helpers ----------------
__device__ __forceinline__ uint32_t smem_u32(const void* p) {
    uint32_t a;
    asm("{ .reg .u64 t; cvta.to.shared.u64 t, %1; cvt.u32.u64 %0, t; }" : "=r"(a) : "l"(p));
    return a;
}
__device__ __forceinline__ void cp_async16(uint32_t dst, const void* src) {
    asm volatile("cp.async.cg.shared.global [%0], [%1], 16;" :: "r"(dst), "l"(src));
}
__device__ __forceinline__ void cp_commit() { asm volatile("cp.async.commit_group;"); }
__device__ __forceinline__ void cp_wait0() { asm volatile("cp.async.wait_group 0;" ::: "memory"); }

__device__ __forceinline__ void ldsm4(uint32_t* r, uint32_t addr) {
    asm volatile("ldmatrix.sync.aligned.m8n8.x4.shared.b16 {%0,%1,%2,%3}, [%4];"
        : "=r"(r[0]), "=r"(r[1]), "=r"(r[2]), "=r"(r[3]) : "r"(addr));
}
__device__ __forceinline__ void mma16816(float* d, const uint32_t* a, uint32_t b0, uint32_t b1) {
    asm volatile(
        "mma.sync.aligned.m16n8k16.row.col.f32.f16.f16.f32 "
        "{%0,%1,%2,%3}, {%4,%5,%6,%7}, {%8,%9}, {%0,%1,%2,%3};"
        : "+f"(d[0]), "+f"(d[1]), "+f"(d[2]), "+f"(d[3])
        : "r"(a[0]), "r"(a[1]), "r"(a[2]), "r"(a[3]), "r"(b0), "r"(b1));
}

// ---------------- prep kernels ----------------
__global__ void prep_x_kernel(const float* __restrict__ x) {
    int idx = blockIdx.x * blockDim.x + threadIdx.x;
    if (idx >= HP * WP) return;
    const int yy = idx / WP, xp = idx % WP;
    int sy = yy - 1; sy = (sy < 0) ? 1 : ((sy > H_IMG - 1) ? (H_IMG - 2) : sy);
    int sx = xp - 1; sx = (sx < 0) ? 1 : ((sx > W_IMG - 1) ? (W_IMG - 2) : sx);
    const float* src = x + (size_t)sy * W_IMG + sx;
    uint4* oh = (uint4*)(g_xh + (size_t)idx * 128);
    const int sw = xp & 7;
#pragma unroll
    for (int chunk = 0; chunk < 8; chunk++) {
        const int cig = chunk ^ sw;
        uint32_t h[4];
#pragma unroll
        for (int j = 0; j < 4; j++) {
            const float a = src[(size_t)(cig * 8 + 2 * j) * (H_IMG * W_IMG)];
            const float b = src[(size_t)(cig * 8 + 2 * j + 1) * (H_IMG * W_IMG)];
            h[j] = (uint32_t)__half_as_ushort(__float2half_rn(a)) |
                   ((uint32_t)__half_as_ushort(__float2half_rn(b)) << 16);
        }
        oh[chunk] = make_uint4(h[0], h[1], h[2], h[3]);
    }
}

__global__ void prep_w_kernel(const float* __restrict__ wgt) {  // [128oc][64ci][3][3]
    int idx = blockIdx.x * blockDim.x + threadIdx.x;   // (t, n, chunk)
    if (idx >= 9 * 128 * 8) return;
    const int chunk = idx & 7;
    const int n = (idx >> 3) & 127;
    const int t = idx >> 10;
    uint4* oh = (uint4*)(g_bwh + ((size_t)t * 128 + n) * 128) + chunk;
    const int cig = chunk ^ (n & 7);
    uint32_t h[4];
#pragma unroll
    for (int j = 0; j < 4; j++) {
        const float a = wgt[(size_t)n * 576 + (cig * 8 + 2 * j) * 9 + t];
        const float b = wgt[(size_t)n * 576 + (cig * 8 + 2 * j + 1) * 9 + t];
        h[j] = (uint32_t)__half_as_ushort(__float2half_rn(a)) |
               ((uint32_t)__half_as_ushort(__float2half_rn(b)) << 16);
    }
    *oh = make_uint4(h[0], h[1], h[2], h[3]);
}

// ---------------- main MMA kernel ----------------
// SMEM:
//  A:     [0,      66560)   4 dy-rows x 130 px x 128B (fp16)
//  B:     [66560,  99328)   2 x 16KB double buffer
//  C stage (reuses [0, 133120)): 128 oc x 260 floats
//  scale: [133120, 133632)   -- PAST the C region (R12 bug fix)
//  shift: [133632, 134144)
#define OFF_A  0
#define OFF_B  66560
#define OFF_SCALE 133120
#define OFF_SHIFT 133632
#define SMEM_NEED 134144
#define CSTR 260

__global__ void __launch_bounds__(NTHR, 1) conv_mma_kernel(
    const float* __restrict__ gamma, const float* __restrict__ beta,
    const float* __restrict__ mean, const float* __restrict__ var,
    const int* __restrict__ mask, float* __restrict__ out) {
    extern __shared__ __align__(128) char sgen[];
    const uint32_t sb = smem_u32(sgen);
    float* s_scale = (float*)(sgen + OFF_SCALE);
    float* s_shift = (float*)(sgen + OFF_SHIFT);

    const int tid = threadIdx.x;
    const int wid = tid >> 5, lid = tid & 31;
    const int warpM = wid & 3;        // 4 m-frag groups (64 px each over 2 rows)
    const int warpN = wid >> 2;       // 2 n-groups (64 oc each)
    const int rowSel = warpM >> 1;
    const int px0 = (warpM & 1) * 64;
    const int y0 = (blockIdx.x >> 2) * 2;
    const int x0 = (blockIdx.x & 3) << 7;

    if (tid < COUT) {
        const float inv = rsqrtf(var[tid] + 1e-5f);
        const float sc = gamma[tid] * inv;
        s_scale[tid] = sc;
        s_shift[tid] = beta[tid] - mean[tid] * sc;
    }

    // ---- stage A halo: 4 dy-rows x 130 px (rows pre-swizzled in gmem) ----
    for (int rid = tid; rid < 4 * 130; rid += NTHR) {
        const int dy = rid / 130, pxl = rid % 130;
        const unsigned char* src = g_xh + ((size_t)((y0 + dy) * WP + (x0 + pxl))) * 128;
        const uint32_t dst = sb + OFF_A + (uint32_t)(dy * 130 + pxl) * 128;
#pragma unroll
        for (int c = 0; c < 8; c++) cp_async16(dst + c * 16, src + c * 16);
    }
    // ---- stage B tap 0 into buf 0 (16KB) ----
    for (int i = tid; i < 1024; i += NTHR) {
        cp_async16(sb + OFF_B + i * 16, g_bwh + (size_t)i * 16);
    }
    cp_commit();
    cp_wait0();
    __syncthreads();

    float acc[4][8][4];
#pragma unroll
    for (int mf = 0; mf < 4; mf++)
#pragma unroll
        for (int nf = 0; nf < 8; nf++)
#pragma unroll
            for (int e = 0; e < 4; e++) acc[mf][nf][e] = 0.0f;

    const int a_rowpart = (lid & 7) + ((lid >> 3) & 1) * 8;
    const int a_cs = (lid >> 4) & 1;
    const int b_rowpart = (lid & 7) + ((lid >> 4) & 1) * 8;
    const int b_cs = (lid >> 3) & 1;
    const int b_swz = lid & 7;

    for (int t = 0; t < 9; t++) {
        const int dy = t / 3, dx = t % 3;
        const int buf = t & 1;

        if (t < 8) {
            const int nb = (t + 1) & 1;
            for (int i = tid; i < 1024; i += NTHR) {
                cp_async16(sb + OFF_B + nb * 16384 + i * 16,
                           g_bwh + ((size_t)(t + 1) * 16384) + (size_t)i * 16);
            }
            cp_commit();
        }

        const int pixbase = px0 + dx + a_rowpart;
        const int a_swz = (a_rowpart + dx) & 7;
        const uint32_t a_row = sb + OFF_A + (uint32_t)((dy + rowSel) * 130 + pixbase) * 128;
        const uint32_t b_base = sb + OFF_B + buf * 16384;
        uint32_t b_addr[4];
#pragma unroll
        for (int nfp = 0; nfp < 4; nfp++) {
            b_addr[nfp] = b_base + (uint32_t)(warpN * 64 + nfp * 16 + b_rowpart) * 128;
        }

#pragma unroll
        for (int ks = 0; ks < 4; ks++) {
            uint32_t bh[16];
            const uint32_t bco = (uint32_t)(((ks * 2 + b_cs) ^ b_swz) << 4);
#pragma unroll
            for (int nfp = 0; nfp < 4; nfp++) {
                ldsm4(bh + nfp * 4, b_addr[nfp] + bco);
            }
            const uint32_t aco = (uint32_t)(((ks * 2 + a_cs) ^ a_swz) << 4);
#pragma unroll
            for (int mf = 0; mf < 4; mf++) {
                uint32_t ah[4];
                ldsm4(ah, a_row + (uint32_t)mf * 2048 + aco);
#pragma unroll
                for (int nf = 0; nf < 8; nf++) {
                    mma16816(acc[mf][nf], ah, bh[nf * 2], bh[nf * 2 + 1]);
                }
            }
        }

        if (t < 8) {
            cp_wait0();
            __syncthreads();
        }
    }

    __syncthreads();  // all warps done reading A/B before C staging reuses smem

    // ---- stage C = [oc][m 256] fp32 in smem, then coalesced epilogue ----
    float* C = (float*)sgen;  // [0, 133120) — does NOT touch scale/shift now
#pragma unroll
    for (int mf = 0; mf < 4; mf++) {
        const int m0 = rowSel * 128 + px0 + mf * 16 + (lid >> 2);
#pragma unroll
        for (int nf = 0; nf < 8; nf++) {
            const int oc = warpN * 64 + nf * 8 + (lid & 3) * 2;
            C[oc * CSTR + m0]           = acc[mf][nf][0];
            C[(oc + 1) * CSTR + m0]     = acc[mf][nf][1];
            C[oc * CSTR + m0 + 8]       = acc[mf][nf][2];
            C[(oc + 1) * CSTR + m0 + 8] = acc[mf][nf][3];
        }
    }
    __syncthreads();

    for (int q = tid; q < 128 * 64; q += NTHR) {
        const int oc = q >> 6;
        const int pxq = (q & 63) * 4;
        const int row = pxq >> 7;
        const int xq = pxq & 127;
        const float4 v = *(const float4*)(C + oc * CSTR + pxq);
        const float sc = s_scale[oc], sh = s_shift[oc];
        const size_t gidx = (size_t)oc * (H_IMG * W_IMG) + (size_t)(y0 + row) * W_IMG + x0 + xq;
        const int4 m = *(const int4*)(mask + gidx);
        float4 r;
        float tv;
        tv = v.x * sc + sh; tv = (tv >= 0.0f) ? tv : 0.01f * tv; r.x = tv * (float)m.x;
        tv = v.y * sc + sh; tv = (tv >= 0.0f) ? tv : 0.01f * tv; r.y = tv * (float)m.y;
        tv = v.z * sc + sh; tv = (tv >= 0.0f) ? tv : 0.01f * tv; r.z = tv * (float)m.z;
        tv = v.w * sc + sh; tv = (tv >= 0.0f) ? tv : 0.01f * tv; r.w = tv * (float)m.w;
        *(float4*)(out + gidx) = r;
    }
}

// ---------------- host launch ----------------
extern "C" void kernel_launch(void* const* d_in, const int* in_sizes, int n_in,
                              void* d_out, int out_size) {
    const float* x     = (const float*)d_in[0];
    const float* wgt   = (const float*)d_in[1];
    const float* gamma = (const float*)d_in[2];
    const float* beta  = (const float*)d_in[3];
    const float* mean  = (const float*)d_in[4];
    const float* var   = (const float*)d_in[5];
    const int*   mask  = (const int*)d_in[6];
    float* out = (float*)d_out;

    cudaFuncSetAttribute(conv_mma_kernel, cudaFuncAttributeMaxDynamicSharedMemorySize, SMEM_NEED);

    prep_w_kernel<<<(9 * 128 * 8 + 127) / 128, 128>>>(wgt);
    prep_x_kernel<<<(HP * WP + 255) / 256, 256>>>(x);
    conv_mma_kernel<<<1024, NTHR, SMEM_NEED>>>(gamma, beta, mean, var, mask, out);
}